// round 6
// baseline (speedup 1.0000x reference)
#include <cuda_runtime.h>
#include <math.h>

#define PS 16
#define PH 64
#define PW 64
#define NPATCH (PH*PW)
#define NB 32
#define IH 1024
#define IW 1024
#define IMGSZ (IH*IW)           // floats per image
#define TROW 17                 // padded tile row stride
#define TBATCH 280              // padded per-batch slice (>=16*17, bank-skewed)

__device__ __forceinline__ float clamp01(float x) {
    return fminf(fmaxf(x, 0.0f), 1.0f);
}

// ---------------------------------------------------------------------------
// One CTA = one patch position (sy,px), all 32 batches. 256 threads.
// Thread t owns pixel (r=t>>4, c=t&15) of the patch in every batch.
// All pixel data lives in the smem tile only (no big register arrays) so
// 6 CTAs/SM co-reside (launch_bounds(256,6), regs<=42).
//  Phase 1: 32 coalesced LDG -> STS (pipelined by ptxas).
//  Phase 2: stats: thread (b=t>>3, j=t&7) sums rows 2j,2j+1 of batch b,
//           width-8 shfl reduce -> per-b quality/mean.
//  Phase 3: thread 0 reduces over b, computes code/scale/mpp (in-CTA).
//  Phase 4: apply (CTA-uniform branch) reading the tile, coalesced stores.
// ---------------------------------------------------------------------------
__global__ void __launch_bounds__(256, 6)
fused_kernel(const float* __restrict__ img,
             const float* __restrict__ noise,
             const float* __restrict__ r_strong,
             const float* __restrict__ r_drop,
             const float* __restrict__ r_else,
             const float* __restrict__ bright_f,
             const float* __restrict__ contrast_f,
             const float* __restrict__ slight_f,
             const int*   __restrict__ aug_choice,
             const int*   __restrict__ slight_choice,
             float* __restrict__ out) {
    __shared__ float tile[NB * TBATCH];       // 35.0 KB staged patch data
    __shared__ float s_qual[NB];
    __shared__ float s_mean[NB];
    __shared__ int   s_code;
    __shared__ float s_scale;
    __shared__ float s_mpp;

    const int p  = blockIdx.x;                // patch index 0..4095
    const int sy = p >> 6;
    const int px = p & 63;
    const int t  = threadIdx.x;
    const int r  = t >> 4;
    const int c  = t & 15;

    const size_t pbase = ((size_t)(sy * PS + r)) * IW + px * PS + c;
    const int    toff  = r * TROW + c;

    // ---- Phase 1: load all batches (coalesced 64B segments) into smem ----
#pragma unroll 8
    for (int b = 0; b < NB; ++b)
        tile[b * TBATCH + toff] = img[pbase + (size_t)b * IMGSZ];
    __syncthreads();

    // ---- Phase 2: per-(b,patch) stats ----
    {
        const int bb = t >> 3;                // batch this thread reduces
        const int j  = t & 7;                 // row-pair 2j, 2j+1
        const float* trow = tile + bb * TBATCH + (2 * j) * TROW;
        float s = 0.f, ss = 0.f;
#pragma unroll
        for (int k = 0; k < 2; ++k) {
#pragma unroll
            for (int cc = 0; cc < PS; ++cc) {
                float x = trow[k * TROW + cc];
                s  += x;
                ss  = fmaf(x, x, ss);
            }
        }
#pragma unroll
        for (int off = 4; off >= 1; off >>= 1) {
            s  += __shfl_down_sync(0xffffffffu, s,  off, 8);
            ss += __shfl_down_sync(0xffffffffu, ss, off, 8);
        }
        if (j == 0) {
            float mean = s * (1.0f / 256.0f);
            float var  = (ss - s * s * (1.0f / 256.0f)) * (1.0f / 255.0f); // ddof=1
            var = fmaxf(var, 0.0f);
            float std_ = sqrtf(var);
            float iq   = 1.0f - 2.0f * fabsf(mean - 0.5f);
            s_qual[bb] = (std_ + iq + var) * (1.0f / 3.0f);
            s_mean[bb] = mean;
        }
    }
    __syncthreads();

    // ---- Phase 3: batch reduce + code (thread 0) ----
    if (t == 0) {
        float q = 0.f, m = 0.f;
#pragma unroll
        for (int b = 0; b < NB; ++b) { q += s_qual[b]; m += s_mean[b]; }
        q *= (1.0f / NB);
        m *= (1.0f / NB);

        bool low    = q < 0.7f;
        bool strong = low  && (r_strong[p] < 0.8f);
        bool drop   = low  && (q < 0.3f) && (r_drop[p] < 0.1f);
        bool els    = !low && (r_else[p] < 0.3f);

        int code = 0;
        if (strong) code = aug_choice[p] + 1;      // 1..4
        if (els)    code = slight_choice[p] + 5;   // 5..6
        if (drop)   code = 7;

        float scale = 0.f;
        if      (code == 1) scale = 0.1f;
        else if (code == 3) scale = bright_f[p];
        else if (code == 4) scale = contrast_f[p];
        else if (code == 5) scale = 0.05f;
        else if (code == 6) scale = slight_f[p];

        s_code  = code;
        s_scale = scale;
        s_mpp   = m;
    }
    __syncthreads();

    const int   code  = s_code;               // uniform across CTA
    const float scale = s_scale;
    const float mpp   = s_mpp;

    // ---- Phase 4: apply + store (fully coalesced, same pattern as load) ----
    if (code == 0) {
#pragma unroll 8
        for (int b = 0; b < NB; ++b)
            __stcs(&out[pbase + (size_t)b * IMGSZ], tile[b * TBATCH + toff]);
    } else if (code == 7) {
#pragma unroll 8
        for (int b = 0; b < NB; ++b)
            __stcs(&out[pbase + (size_t)b * IMGSZ], 0.0f);
    } else if (code == 2) {
        // 3x3 zero-padded blur confined to the patch, from the smem tile.
#pragma unroll 4
        for (int b = 0; b < NB; ++b) {
            const float* tb = tile + b * TBATCH;
            float sum = 0.f;
#pragma unroll
            for (int dy = -1; dy <= 1; ++dy) {
                const int rr = r + dy;
                if (rr < 0 || rr >= PS) continue;
#pragma unroll
                for (int dx = -1; dx <= 1; ++dx) {
                    const int cc = c + dx;
                    if (cc < 0 || cc >= PS) continue;
                    sum += tb[rr * TROW + cc];
                }
            }
            __stcs(&out[pbase + (size_t)b * IMGSZ], sum * (1.0f / 9.0f));
        }
    } else if (code == 1 || code == 5) {
#pragma unroll 8
        for (int b = 0; b < NB; ++b) {
            float n = noise[pbase + (size_t)b * IMGSZ];
            __stcs(&out[pbase + (size_t)b * IMGSZ],
                   clamp01(fmaf(n, scale, tile[b * TBATCH + toff])));
        }
    } else if (code == 3 || code == 6) {
#pragma unroll 8
        for (int b = 0; b < NB; ++b)
            __stcs(&out[pbase + (size_t)b * IMGSZ],
                   clamp01(tile[b * TBATCH + toff] * scale));
    } else { // code == 4 (contrast)
#pragma unroll 8
        for (int b = 0; b < NB; ++b)
            __stcs(&out[pbase + (size_t)b * IMGSZ],
                   clamp01(fmaf(tile[b * TBATCH + toff] - mpp, scale, mpp)));
    }
}

extern "C" void kernel_launch(void* const* d_in, const int* in_sizes, int n_in,
                              void* d_out, int out_size) {
    const float* img           = (const float*)d_in[0];
    const float* noise         = (const float*)d_in[1];
    const float* r_strong      = (const float*)d_in[2];
    const float* r_drop        = (const float*)d_in[3];
    const float* r_else        = (const float*)d_in[4];
    const float* bright_f      = (const float*)d_in[5];
    const float* contrast_f    = (const float*)d_in[6];
    const float* slight_f      = (const float*)d_in[7];
    const int*   aug_choice    = (const int*)d_in[8];
    const int*   slight_choice = (const int*)d_in[9];
    float* out = (float*)d_out;

    fused_kernel<<<NPATCH, 256>>>(img, noise, r_strong, r_drop, r_else,
                                  bright_f, contrast_f, slight_f,
                                  aug_choice, slight_choice, out);
}

// round 7
// speedup vs baseline: 1.1055x; 1.1055x over previous
#include <cuda_runtime.h>
#include <math.h>

#define PS 16
#define NB 32
#define IH 1024
#define IW 1024
#define IMGSZ (IH*IW)
#define TROW 33                   // padded row stride within a batch slice
#define TBATCH (PS*TROW)          // 528 floats per batch slice
#define TILE_BYTES (NB*TBATCH*4)  // 67584 B dynamic smem

__device__ __forceinline__ float clamp01(float x) {
    return fminf(fmaxf(x, 0.0f), 1.0f);
}

// ---------------------------------------------------------------------------
// One CTA = one PATCH-PAIR (sy, 2k / 2k+1), all 32 batches. 512 threads:
// c2 = t&31 (column across the pair -> dense 128 B per warp), r = t>>5.
//  Phase 1: 32 dense coalesced LDG -> STS (unroll 16, MLP=16).
//  Phase 2: stats: thread (pb=t>>3 -> patch,b ; j=t&7) sums rows 2j,2j+1,
//           width-8 shfl reduce -> per-(patch,b) quality/mean.
//  Phase 3: threads 0,1 reduce over b, compute per-patch code -> (alpha,
//           beta, delta, isblur) coefficients.
//  Phase 4: apply from tile, dense 128 B streaming stores.
// ---------------------------------------------------------------------------
__global__ void __launch_bounds__(512, 3)
fused_kernel(const float* __restrict__ img,
             const float* __restrict__ noise,
             const float* __restrict__ r_strong,
             const float* __restrict__ r_drop,
             const float* __restrict__ r_else,
             const float* __restrict__ bright_f,
             const float* __restrict__ contrast_f,
             const float* __restrict__ slight_f,
             const int*   __restrict__ aug_choice,
             const int*   __restrict__ slight_choice,
             float* __restrict__ out) {
    extern __shared__ float tile[];           // [NB][16][33]
    __shared__ float s_qual[2][NB];
    __shared__ float s_mean[2][NB];
    __shared__ int   s_code[2];
    __shared__ float s_alpha[2], s_beta[2], s_delta[2];

    const int bx   = blockIdx.x;              // 0..2047
    const int sy   = bx >> 5;                 // patch row 0..63
    const int pair = bx & 31;                 // pair index 0..31
    const int t    = threadIdx.x;
    const int c2   = t & 31;                  // col across pair (0..31)
    const int r    = (t >> 5) & 15;           // row 0..15

    const int gidx = (sy * PS + r) * IW + pair * 32 + c2;   // fits in int
    const int toff = r * TROW + c2;

    // ---- Phase 1: dense loads into smem (1 wavefront per warp-load) ----
#pragma unroll 16
    for (int b = 0; b < NB; ++b)
        tile[b * TBATCH + toff] = img[gidx + b * IMGSZ];
    __syncthreads();

    // ---- Phase 2: per-(patch,b) stats ----
    {
        const int pb    = t >> 3;             // 0..63
        const int patch = pb >> 5;            // 0..1
        const int b     = pb & 31;
        const int j     = t & 7;              // row-pair 2j,2j+1
        const float* trow = tile + b * TBATCH + (2 * j) * TROW + patch * PS;
        float s = 0.f, ss = 0.f;
#pragma unroll
        for (int k = 0; k < 2; ++k) {
#pragma unroll
            for (int cc = 0; cc < PS; ++cc) {
                float x = trow[k * TROW + cc];
                s  += x;
                ss  = fmaf(x, x, ss);
            }
        }
#pragma unroll
        for (int off = 4; off >= 1; off >>= 1) {
            s  += __shfl_down_sync(0xffffffffu, s,  off, 8);
            ss += __shfl_down_sync(0xffffffffu, ss, off, 8);
        }
        if (j == 0) {
            float mean = s * (1.0f / 256.0f);
            float var  = (ss - s * s * (1.0f / 256.0f)) * (1.0f / 255.0f); // ddof=1
            var = fmaxf(var, 0.0f);
            float std_ = sqrtf(var);
            float iq   = 1.0f - 2.0f * fabsf(mean - 0.5f);
            s_qual[patch][b] = (std_ + iq + var) * (1.0f / 3.0f);
            s_mean[patch][b] = mean;
        }
    }
    __syncthreads();

    // ---- Phase 3: per-patch batch reduce + code -> coefficients ----
    if (t < 2) {
        const int patch = t;
        const int pg    = sy * 64 + pair * 2 + patch;   // global patch idx
        float q = 0.f, m = 0.f;
#pragma unroll
        for (int b = 0; b < NB; ++b) { q += s_qual[patch][b]; m += s_mean[patch][b]; }
        q *= (1.0f / NB);
        m *= (1.0f / NB);

        bool low    = q < 0.7f;
        bool strong = low  && (r_strong[pg] < 0.8f);
        bool drop   = low  && (q < 0.3f) && (r_drop[pg] < 0.1f);
        bool els    = !low && (r_else[pg] < 0.3f);

        int code = 0;
        if (strong) code = aug_choice[pg] + 1;      // 1..4
        if (els)    code = slight_choice[pg] + 5;   // 5..6
        if (drop)   code = 7;

        // out = clamp01(alpha*v + beta*noise + delta)  (code 2 special-cased)
        float alpha = 1.f, beta = 0.f, delta = 0.f;
        if      (code == 1) beta = 0.1f;
        else if (code == 3) alpha = bright_f[pg];
        else if (code == 4) { float cf = contrast_f[pg]; alpha = cf; delta = m * (1.0f - cf); }
        else if (code == 5) beta = 0.05f;
        else if (code == 6) alpha = slight_f[pg];
        else if (code == 7) alpha = 0.f;

        s_code[patch]  = code;
        s_alpha[patch] = alpha;
        s_beta[patch]  = beta;
        s_delta[patch] = delta;
    }
    __syncthreads();

    // ---- Phase 4: apply + dense streaming stores ----
    const int   patch = c2 >> 4;              // uniform per half-warp
    const int   lc    = c2 & 15;              // col within patch
    const int   code  = s_code[patch];
    const float alpha = s_alpha[patch];
    const float beta  = s_beta[patch];
    const float delta = s_delta[patch];

    if (code == 2) {
        // 3x3 zero-padded blur confined to the patch, from smem.
#pragma unroll 4
        for (int b = 0; b < NB; ++b) {
            const float* tb = tile + b * TBATCH;
            float sum = 0.f;
#pragma unroll
            for (int dy = -1; dy <= 1; ++dy) {
                const int rr = r + dy;
                if (rr < 0 || rr >= PS) continue;
#pragma unroll
                for (int dx = -1; dx <= 1; ++dx) {
                    const int cc = lc + dx;
                    if (cc < 0 || cc >= PS) continue;
                    sum += tb[rr * TROW + c2 + dx];
                }
            }
            __stcs(&out[gidx + b * IMGSZ], sum * (1.0f / 9.0f));
        }
    } else if (beta != 0.0f) {
#pragma unroll 8
        for (int b = 0; b < NB; ++b) {
            float v  = tile[b * TBATCH + toff];
            float nv = noise[gidx + b * IMGSZ];
            __stcs(&out[gidx + b * IMGSZ],
                   clamp01(fmaf(beta, nv, fmaf(alpha, v, delta))));
        }
    } else {
#pragma unroll 8
        for (int b = 0; b < NB; ++b) {
            float v = tile[b * TBATCH + toff];
            __stcs(&out[gidx + b * IMGSZ], clamp01(fmaf(alpha, v, delta)));
        }
    }
}

extern "C" void kernel_launch(void* const* d_in, const int* in_sizes, int n_in,
                              void* d_out, int out_size) {
    const float* img           = (const float*)d_in[0];
    const float* noise         = (const float*)d_in[1];
    const float* r_strong      = (const float*)d_in[2];
    const float* r_drop        = (const float*)d_in[3];
    const float* r_else        = (const float*)d_in[4];
    const float* bright_f      = (const float*)d_in[5];
    const float* contrast_f    = (const float*)d_in[6];
    const float* slight_f      = (const float*)d_in[7];
    const int*   aug_choice    = (const int*)d_in[8];
    const int*   slight_choice = (const int*)d_in[9];
    float* out = (float*)d_out;

    // idempotent; needed for >48KB dynamic smem (ignore error under capture)
    cudaFuncSetAttribute(fused_kernel,
                         cudaFuncAttributeMaxDynamicSharedMemorySize,
                         TILE_BYTES);

    fused_kernel<<<2048, 512, TILE_BYTES>>>(img, noise, r_strong, r_drop,
                                            r_else, bright_f, contrast_f,
                                            slight_f, aug_choice,
                                            slight_choice, out);
}